// round 14
// baseline (speedup 1.0000x reference)
#include <cuda_runtime.h>
#include <cuda_fp16.h>
#include <cstdint>

#define N_NODES  50000
#define N_EDGES  400000
#define N_GRAPHS 500
#define N_FEAT   4
#define EMB      200
#define HID      128
#define ELLW     40                 // ELL width; P(Poisson(8) >= 40) ~ 1e-17

// padded GEMM dims
#define KPAD 208
#define NPAD 208
#define NKP  (KPAD / 2)             // 104 k-pairs

// ---------------- device scratch (no runtime allocation allowed) ----------
__device__ __half g_bufA[(size_t)N_NODES * EMB];
__device__ __half g_bufB[(size_t)N_NODES * EMB];
__device__ __half g_hw  [(size_t)N_NODES * EMB];
__device__ float g_dinv[N_NODES];
__device__ int   g_cur [N_NODES];                    // becomes degree
__device__ int   g_esrc[(size_t)N_NODES * ELLW];     // ELL: src ids
__device__ int2  g_ell [(size_t)N_NODES * ELLW];     // ELL: {src, coef bits}
__device__ int   g_flag_ei;
__device__ int   g_flag_bi;
__device__ int   g_goff[N_GRAPHS + 1];
// packed fp16 hi/lo splits of W1..W3
__device__ uint32_t g_Whi[3][NKP * NPAD];
__device__ uint32_t g_Wlo[3][NKP * NPAD];

__device__ __forceinline__ int ld_idx(const void* p, long long i, int is64) {
    if (is64) return (int)((const long long*)p)[i];
    return ((const int*)p)[i];
}

__device__ __forceinline__ uint32_t pack_h2(__half lo, __half hi) {
    uint16_t a = __half_as_ushort(lo);
    uint16_t b = __half_as_ushort(hi);
    return (uint32_t)a | ((uint32_t)b << 16);
}

// ---------------- A: init + dtype detect + W split (fused) -----------------
__global__ void init_split_kernel(const void* ei, const void* bi,
                                  const float* __restrict__ W1,
                                  const float* __restrict__ W2,
                                  const float* __restrict__ W3) {
    int idx = blockIdx.x * blockDim.x + threadIdx.x;
    if (idx == 0) {
        const int* e32 = (const int*)ei;
        int all0 = 1;
        for (int k = 0; k < 16; k++) if (e32[2 * k + 1] != 0) all0 = 0;
        g_flag_ei = all0;
        const int* b32 = (const int*)bi;
        int all0b = 1;
        for (int k = 0; k < 16; k++) if (b32[2 * (20000 + k) + 1] != 0) all0b = 0;
        g_flag_bi = all0b;
    }
    if (idx < N_NODES) g_cur[idx] = 0;
    int total = NKP * NPAD;
    if (idx < 3 * total) {
        int l = idx / total;
        int r = idx - l * total;
        int kp = r / NPAD, n = r - kp * NPAD;
        const float* W = (l == 0) ? W1 : (l == 1) ? W2 : W3;
        int k0 = 2 * kp, k1 = 2 * kp + 1;
        float w0 = (k0 < EMB && n < EMB) ? W[k0 * EMB + n] : 0.f;
        float w1 = (k1 < EMB && n < EMB) ? W[k1 * EMB + n] : 0.f;
        __half h0 = __float2half_rn(w0);
        __half h1 = __float2half_rn(w1);
        __half l0 = __float2half_rn(w0 - __half2float(h0));
        __half l1 = __float2half_rn(w1 - __half2float(h1));
        g_Whi[l][r] = pack_h2(h0, h1);
        g_Wlo[l][r] = pack_h2(l0, l1);
    }
}

// ---------------- B: ELL scatter (4 edges/thread, atomic bump) -------------
__global__ void ell_scatter_kernel(const void* ei) {
    int t = blockIdx.x * blockDim.x + threadIdx.x;
    int e0 = t * 4;
    if (e0 >= N_EDGES) return;
    int s[4], d[4];
    if (g_flag_ei) {
        const longlong2* ps = (const longlong2*)ei + e0 / 2;
        const longlong2* pd = (const longlong2*)ei + (N_EDGES + e0) / 2;
        longlong2 a = __ldg(ps), b = __ldg(ps + 1);
        longlong2 c = __ldg(pd), e = __ldg(pd + 1);
        s[0] = (int)a.x; s[1] = (int)a.y; s[2] = (int)b.x; s[3] = (int)b.y;
        d[0] = (int)c.x; d[1] = (int)c.y; d[2] = (int)e.x; d[3] = (int)e.y;
    } else {
        int4 a = __ldg((const int4*)((const int*)ei + e0));
        int4 b = __ldg((const int4*)((const int*)ei + N_EDGES + e0));
        s[0] = a.x; s[1] = a.y; s[2] = a.z; s[3] = a.w;
        d[0] = b.x; d[1] = b.y; d[2] = b.z; d[3] = b.w;
    }
#pragma unroll
    for (int q = 0; q < 4; q++) {
        int p = atomicAdd(&g_cur[d[q]], 1);
        if (p < ELLW) g_esrc[(size_t)d[q] * ELLW + p] = s[q];
    }
}

// ---------------- C: finalize (dinv + ELL coefs + graph boundaries) --------
__global__ void finalize_kernel(const void* bi) {
    int i = blockIdx.x * blockDim.x + threadIdx.x;
    if (i >= N_NODES) return;
    int deg = g_cur[i];
    if (deg > ELLW) deg = ELLW;
    float di = rsqrtf((float)(g_cur[i] + 1));
    g_dinv[i] = di;
    const int* es = g_esrc + (size_t)i * ELLW;
    int2* el = g_ell + (size_t)i * ELLW;
    for (int j = 0; j < deg; j++) {
        int s = es[j];
        float ds = rsqrtf((float)(__ldg(&g_cur[s]) + 1));
        el[j] = make_int2(s, __float_as_int(ds * di));
    }
    // graph boundary detection on sorted batch_index
    int is64 = g_flag_bi;
    int b = ld_idx(bi, i, is64);
    if (i == 0) {
        for (int g = 0; g <= b; g++) g_goff[g] = 0;
    }
    if (i == N_NODES - 1) {
        for (int g = b + 1; g <= N_GRAPHS; g++) g_goff[g] = N_NODES;
    } else {
        int bn = ld_idx(bi, i + 1, is64);
        for (int g = b + 1; g <= bn; g++) g_goff[g] = i + 1;
    }
}

// ---------------- D: layer 0 fused — aggregate(x) then (Ax)@W0 -------------
// warp per node: lane-parallel edge gather + shfl reduce, then 25 lanes
// each emit 8 fp16 outputs (bias+leaky fused).
__global__ __launch_bounds__(256) void layer0_kernel(
    const float* __restrict__ x, const float* __restrict__ W0,
    const float* __restrict__ b0, __half* __restrict__ out) {
    int warp = (blockIdx.x * blockDim.x + threadIdx.x) >> 5;
    int lane = threadIdx.x & 31;
    if (warp >= N_NODES) return;
    int i = warp;
    int deg = g_cur[i];
    if (deg > ELLW) deg = ELLW;

    float ax = 0.f, ay = 0.f, az = 0.f, aw = 0.f;
    if (lane == 0) {
        float dv = g_dinv[i];
        float sc = dv * dv;
        float4 xi = *reinterpret_cast<const float4*>(x + (size_t)i * 4);
        ax = sc * xi.x; ay = sc * xi.y; az = sc * xi.z; aw = sc * xi.w;
    }
    const int2* el = g_ell + (size_t)i * ELLW;
    for (int j = lane; j < deg; j += 32) {
        int2 sc2 = __ldg(&el[j]);
        float c = __int_as_float(sc2.y);
        float4 v = *reinterpret_cast<const float4*>(x + (size_t)sc2.x * 4);
        ax += c * v.x; ay += c * v.y; az += c * v.z; aw += c * v.w;
    }
#pragma unroll
    for (int d = 16; d; d >>= 1) {
        ax += __shfl_down_sync(0xffffffffu, ax, d);
        ay += __shfl_down_sync(0xffffffffu, ay, d);
        az += __shfl_down_sync(0xffffffffu, az, d);
        aw += __shfl_down_sync(0xffffffffu, aw, d);
    }
    ax = __shfl_sync(0xffffffffu, ax, 0);
    ay = __shfl_sync(0xffffffffu, ay, 0);
    az = __shfl_sync(0xffffffffu, az, 0);
    aw = __shfl_sync(0xffffffffu, aw, 0);

    if (lane < 25) {
        int f0 = lane * 8;
        uint4 pv;
        uint32_t* pw = reinterpret_cast<uint32_t*>(&pv);
#pragma unroll
        for (int q = 0; q < 4; q++) {
            int f = f0 + 2 * q;
            float s0 = ax * __ldg(&W0[f])
                     + ay * __ldg(&W0[EMB + f])
                     + az * __ldg(&W0[2 * EMB + f])
                     + aw * __ldg(&W0[3 * EMB + f])
                     + __ldg(&b0[f]);
            float s1 = ax * __ldg(&W0[f + 1])
                     + ay * __ldg(&W0[EMB + f + 1])
                     + az * __ldg(&W0[2 * EMB + f + 1])
                     + aw * __ldg(&W0[3 * EMB + f + 1])
                     + __ldg(&b0[f + 1]);
            s0 = s0 > 0.f ? s0 : 0.01f * s0;
            s1 = s1 > 0.f ? s1 : 0.01f * s1;
            __half2 p = __floats2half2_rn(s0, s1);
            pw[q] = *reinterpret_cast<uint32_t*>(&p);
        }
        reinterpret_cast<uint4*>(out)[(size_t)i * 25 + lane] = pv;
    }
}

// ---------------- layers 1-3: fp16x2 split GEMM via mma.sync.m16n8k16 ------
#define GBM   64
#define ASTR  12
#define BSTR  216

#define MMA_F16(d, a0, a1, a2, a3, b0, b1)                                    \
    asm volatile("mma.sync.aligned.m16n8k16.row.col.f32.f16.f16.f32 "        \
                 "{%0,%1,%2,%3}, {%4,%5,%6,%7}, {%8,%9}, {%0,%1,%2,%3};"     \
                 : "+f"((d)[0]), "+f"((d)[1]), "+f"((d)[2]), "+f"((d)[3])    \
                 : "r"(a0), "r"(a1), "r"(a2), "r"(a3), "r"(b0), "r"(b1))

__global__ __launch_bounds__(128) void gemm_f16x2_kernel(
    const __half* __restrict__ h,
    const uint32_t* __restrict__ whi, const uint32_t* __restrict__ wlo,
    __half* __restrict__ out) {
    __shared__ uint32_t sA [2][GBM * ASTR];
    __shared__ uint32_t sBh[2][8 * BSTR];
    __shared__ uint32_t sBl[2][8 * BSTR];

    int tid  = threadIdx.x;
    int lane = tid & 31, warp = tid >> 5;
    int wm = warp >> 1;
    int wn = warp & 1;
    int row0 = blockIdx.x * GBM;
    int gid = lane >> 2;
    int tig = lane & 3;

    float acc[13][2][4];
#pragma unroll
    for (int t = 0; t < 13; t++)
#pragma unroll
        for (int f = 0; f < 2; f++) {
            acc[t][f][0] = 0.f; acc[t][f][1] = 0.f;
            acc[t][f][2] = 0.f; acc[t][f][3] = 0.f;
        }

    uint32_t ra[4];
    uint32_t rbh[13], rbl[13];

    auto FETCH = [&](int chunk) {
        int k0 = chunk * 16;
#pragma unroll
        for (int i = 0; i < 4; i++) {
            int idx = tid + i * 128;
            int r = idx >> 3, kp = idx & 7;
            int gr = row0 + r;
            int ka = k0 + 2 * kp;
            ra[i] = (gr < N_NODES && ka < EMB)
                  ? __ldg(reinterpret_cast<const uint32_t*>(h + (size_t)gr * EMB + ka))
                  : 0u;
        }
        int base = chunk * 8 * NPAD;
#pragma unroll
        for (int i = 0; i < 13; i++) {
            int idx = tid + i * 128;
            int r = idx / NPAD, c = idx - r * NPAD;
            int g = base + r * NPAD + c;
            rbh[i] = __ldg(&whi[g]);
            rbl[i] = __ldg(&wlo[g]);
        }
    };
    auto STORE = [&](int buf) {
#pragma unroll
        for (int i = 0; i < 4; i++) {
            int idx = tid + i * 128;
            int r = idx >> 3, kp = idx & 7;
            sA[buf][r * ASTR + kp] = ra[i];
        }
#pragma unroll
        for (int i = 0; i < 13; i++) {
            int idx = tid + i * 128;
            int r = idx / NPAD, c = idx - r * NPAD;
            sBh[buf][r * BSTR + c] = rbh[i];
            sBl[buf][r * BSTR + c] = rbl[i];
        }
    };

    FETCH(0);
    STORE(0);
    __syncthreads();

    int ar = wm * 32 + gid;
#pragma unroll 1
    for (int ks = 0; ks < 13; ks++) {
        int cur = ks & 1;
        if (ks < 12) FETCH(ks + 1);

        uint32_t a[8];
#pragma unroll
        for (int f = 0; f < 2; f++) {
            int r = ar + f * 16;
            a[f * 4 + 0] = sA[cur][r * ASTR + tig];
            a[f * 4 + 1] = sA[cur][(r + 8) * ASTR + tig];
            a[f * 4 + 2] = sA[cur][r * ASTR + tig + 4];
            a[f * 4 + 3] = sA[cur][(r + 8) * ASTR + tig + 4];
        }

#pragma unroll
        for (int t = 0; t < 13; t++) {
            int n = wn * 104 + t * 8 + gid;
            uint32_t bh0 = sBh[cur][tig * BSTR + n];
            uint32_t bh1 = sBh[cur][(tig + 4) * BSTR + n];
            uint32_t bl0 = sBl[cur][tig * BSTR + n];
            uint32_t bl1 = sBl[cur][(tig + 4) * BSTR + n];
            MMA_F16(acc[t][0], a[0], a[1], a[2], a[3], bh0, bh1);
            MMA_F16(acc[t][1], a[4], a[5], a[6], a[7], bh0, bh1);
            MMA_F16(acc[t][0], a[0], a[1], a[2], a[3], bl0, bl1);
            MMA_F16(acc[t][1], a[4], a[5], a[6], a[7], bl0, bl1);
        }

        if (ks < 12) STORE(cur ^ 1);
        __syncthreads();
    }

#pragma unroll
    for (int t = 0; t < 13; t++) {
        int n = wn * 104 + t * 8 + 2 * tig;
        if (n >= EMB) continue;
#pragma unroll
        for (int f = 0; f < 2; f++) {
            int r = row0 + wm * 32 + f * 16 + gid;
            if (r < N_NODES) {
                __half2 v = __floats2half2_rn(acc[t][f][0], acc[t][f][1]);
                *reinterpret_cast<__half2*>(&out[(size_t)r * EMB + n]) = v;
            }
            if (r + 8 < N_NODES) {
                __half2 v = __floats2half2_rn(acc[t][f][2], acc[t][f][3]);
                *reinterpret_cast<__half2*>(&out[(size_t)(r + 8) * EMB + n]) = v;
            }
        }
    }
}

// ---------------- edge aggregation (fp16 gather, warp per dst node) --------
__device__ __forceinline__ void unpack8(uint4 v, float* f) {
    float2 t;
    t = __half22float2(*reinterpret_cast<__half2*>(&v.x)); f[0] = t.x; f[1] = t.y;
    t = __half22float2(*reinterpret_cast<__half2*>(&v.y)); f[2] = t.x; f[3] = t.y;
    t = __half22float2(*reinterpret_cast<__half2*>(&v.z)); f[4] = t.x; f[5] = t.y;
    t = __half22float2(*reinterpret_cast<__half2*>(&v.w)); f[6] = t.x; f[7] = t.y;
}

__global__ __launch_bounds__(256) void aggregate_h_kernel(
    const __half* __restrict__ hw, const float* __restrict__ b,
    __half* __restrict__ out) {
    int warp = (blockIdx.x * blockDim.x + threadIdx.x) >> 5;
    int lane = threadIdx.x & 31;
    if (warp >= N_NODES || lane >= 25) return;
    int i = warp;

    int deg = g_cur[i];
    if (deg > ELLW) deg = ELLW;
    float dv = g_dinv[i];
    float selfc = dv * dv;

    const uint4* h4 = reinterpret_cast<const uint4*>(hw);
    float acc[8], f[8];
    {
        uint4 v = __ldg(&h4[(size_t)i * 25 + lane]);
        unpack8(v, f);
#pragma unroll
        for (int j = 0; j < 8; j++) acc[j] = selfc * f[j];
    }

    const int2* el = g_ell + (size_t)i * ELLW;
    for (int e = 0; e < deg; e++) {
        int2 sc = __ldg(&el[e]);
        int   s = sc.x;
        float c = __int_as_float(sc.y);
        uint4 v = __ldg(&h4[(size_t)s * 25 + lane]);
        unpack8(v, f);
#pragma unroll
        for (int j = 0; j < 8; j++) acc[j] += c * f[j];
    }

    int f0 = lane * 8;
    float4 b0 = *reinterpret_cast<const float4*>(b + f0);
    float4 b1 = *reinterpret_cast<const float4*>(b + f0 + 4);
    acc[0] += b0.x; acc[1] += b0.y; acc[2] += b0.z; acc[3] += b0.w;
    acc[4] += b1.x; acc[5] += b1.y; acc[6] += b1.z; acc[7] += b1.w;
#pragma unroll
    for (int j = 0; j < 8; j++) acc[j] = acc[j] > 0.f ? acc[j] : 0.01f * acc[j];

    uint4 pv;
    __half2 p;
    p = __floats2half2_rn(acc[0], acc[1]); pv.x = *reinterpret_cast<uint32_t*>(&p);
    p = __floats2half2_rn(acc[2], acc[3]); pv.y = *reinterpret_cast<uint32_t*>(&p);
    p = __floats2half2_rn(acc[4], acc[5]); pv.z = *reinterpret_cast<uint32_t*>(&p);
    p = __floats2half2_rn(acc[6], acc[7]); pv.w = *reinterpret_cast<uint32_t*>(&p);
    reinterpret_cast<uint4*>(out)[(size_t)i * 25 + lane] = pv;
}

// ---------------- E: pooling + MLP head (fused, block per graph) -----------
__global__ __launch_bounds__(256) void poolmlp_kernel(
    const __half* __restrict__ h, const float* __restrict__ xs,
    const float* __restrict__ Wl1, const float* __restrict__ bl1,
    const float* __restrict__ Wl2, const float* __restrict__ bl2,
    float* __restrict__ out) {
    int g = blockIdx.x;
    int t = threadIdx.x;
    __shared__ float gv[EMB + N_FEAT];
    __shared__ float red[HID];

    int r0 = g_goff[g];
    int n  = g_goff[g + 1] - r0;
    if (t < EMB) {
        float s = 0.f;
        for (int j = 0; j < n; j++) s += __half2float(h[(size_t)(r0 + j) * EMB + t]);
        gv[t] = s / fmaxf((float)n, 1.0f);
    } else if (t < EMB + N_FEAT) {
        gv[t] = xs[g * N_FEAT + (t - EMB)];
    }
    __syncthreads();

    if (t < HID) {
        float acc = bl1[t];
        for (int k = 0; k < EMB + N_FEAT; k++) acc += gv[k] * Wl1[k * HID + t];
        acc = acc > 0.f ? acc : 0.01f * acc;
        red[t] = acc * Wl2[t];
    }
    __syncthreads();
    for (int s = HID / 2; s > 0; s >>= 1) {
        if (t < s) red[t] += red[t + s];
        __syncthreads();
    }
    if (t == 0) out[g] = red[0] + bl2[0];
}

// ---------------- launcher --------------------------------------------------
extern "C" void kernel_launch(void* const* d_in, const int* in_sizes, int n_in,
                              void* d_out, int out_size) {
    const float* x        = (const float*)d_in[0];
    const void*  ei       = d_in[1];
    const float* x_scalar = (const float*)d_in[2];
    const void*  bi       = d_in[3];
    const float* W0  = (const float*)d_in[4];
    const float* b0  = (const float*)d_in[5];
    const float* W1  = (const float*)d_in[6];
    const float* b1  = (const float*)d_in[7];
    const float* W2  = (const float*)d_in[8];
    const float* b2  = (const float*)d_in[9];
    const float* W3  = (const float*)d_in[10];
    const float* b3  = (const float*)d_in[11];
    const float* Wl1 = (const float*)d_in[12];
    const float* bl1 = (const float*)d_in[13];
    const float* Wl2 = (const float*)d_in[14];
    const float* bl2 = (const float*)d_in[15];
    float* out = (float*)d_out;

    __half *bufA, *bufB, *hw;
    uint32_t *whi, *wlo;
    cudaGetSymbolAddress((void**)&bufA, g_bufA);
    cudaGetSymbolAddress((void**)&bufB, g_bufB);
    cudaGetSymbolAddress((void**)&hw,   g_hw);
    cudaGetSymbolAddress((void**)&whi,  g_Whi);
    cudaGetSymbolAddress((void**)&wlo,  g_Wlo);

    const int TB = 256;
    int splitTot = 3 * NKP * NPAD;                       // 64896
    int gridA  = (splitTot + TB - 1) / TB;               // covers N_NODES too
    int gridB  = (N_EDGES / 4 + TB - 1) / TB;            // 391
    int gridC  = (N_NODES + TB - 1) / TB;                // 196
    int gridD  = (N_NODES * 32 + TB - 1) / TB;           // 6250 (warp/node)
    int gridGm = (N_NODES + GBM - 1) / GBM;              // 782

    const int WTOT = NKP * NPAD;

    // preprocessing (3 launches)
    init_split_kernel<<<gridA, TB>>>(ei, bi, W1, W2, W3);
    ell_scatter_kernel<<<gridB, TB>>>(ei);
    finalize_kernel<<<gridC, TB>>>(bi);

    // layer 0 (fused aggregate + gemm0 + bias + leaky)
    layer0_kernel<<<gridD, TB>>>(x, W0, b0, bufA);

    // layer 1
    gemm_f16x2_kernel<<<gridGm, 128>>>(bufA, whi, wlo, hw);
    aggregate_h_kernel<<<gridD, TB>>>(hw, b1, bufB);
    // layer 2
    gemm_f16x2_kernel<<<gridGm, 128>>>(bufB, whi + WTOT, wlo + WTOT, hw);
    aggregate_h_kernel<<<gridD, TB>>>(hw, b2, bufA);
    // layer 3
    gemm_f16x2_kernel<<<gridGm, 128>>>(bufA, whi + 2 * WTOT, wlo + 2 * WTOT, hw);
    aggregate_h_kernel<<<gridD, TB>>>(hw, b3, bufB);

    // pool + MLP head (fused)
    poolmlp_kernel<<<N_GRAPHS, TB>>>(bufB, x_scalar, Wl1, bl1, Wl2, bl2, out);
}

// round 15
// speedup vs baseline: 1.1159x; 1.1159x over previous
#include <cuda_runtime.h>
#include <cuda_fp16.h>
#include <cstdint>

#define N_NODES  50000
#define N_EDGES  400000
#define N_GRAPHS 500
#define N_FEAT   4
#define EMB      200
#define HID      128
#define ELLW     40                 // ELL width; P(Poisson(8) >= 40) ~ 1e-17

// padded GEMM dims
#define KPAD 208
#define NPAD 208
#define NKP  (KPAD / 2)             // 104 k-pairs

// ---------------- device scratch (no runtime allocation allowed) ----------
__device__ __half g_bufA[(size_t)N_NODES * EMB];
__device__ __half g_bufB[(size_t)N_NODES * EMB];
__device__ __half g_hw  [(size_t)N_NODES * EMB];
__device__ float  g_aggx[(size_t)N_NODES * 4];
__device__ float g_dinv[N_NODES];
__device__ int   g_cur [N_NODES];                    // becomes degree
__device__ int   g_esrc[(size_t)N_NODES * ELLW];     // ELL: src ids
__device__ int2  g_ell [(size_t)N_NODES * ELLW];     // ELL: {src, coef bits}
__device__ int   g_flag_ei;
__device__ int   g_flag_bi;
__device__ int   g_goff[N_GRAPHS + 1];
// packed fp16 hi/lo splits of W1..W3
__device__ uint32_t g_Whi[3][NKP * NPAD];
__device__ uint32_t g_Wlo[3][NKP * NPAD];

__device__ __forceinline__ int ld_idx(const void* p, long long i, int is64) {
    if (is64) return (int)((const long long*)p)[i];
    return ((const int*)p)[i];
}

__device__ __forceinline__ uint32_t pack_h2(__half lo, __half hi) {
    uint16_t a = __half_as_ushort(lo);
    uint16_t b = __half_as_ushort(hi);
    return (uint32_t)a | ((uint32_t)b << 16);
}

// ---------------- A: init + dtype detect + W split (fused) -----------------
__global__ void init_split_kernel(const void* ei, const void* bi,
                                  const float* __restrict__ W1,
                                  const float* __restrict__ W2,
                                  const float* __restrict__ W3) {
    int idx = blockIdx.x * blockDim.x + threadIdx.x;
    if (idx == 0) {
        const int* e32 = (const int*)ei;
        int all0 = 1;
        for (int k = 0; k < 16; k++) if (e32[2 * k + 1] != 0) all0 = 0;
        g_flag_ei = all0;
        const int* b32 = (const int*)bi;
        int all0b = 1;
        for (int k = 0; k < 16; k++) if (b32[2 * (20000 + k) + 1] != 0) all0b = 0;
        g_flag_bi = all0b;
    }
    if (idx < N_NODES) g_cur[idx] = 0;
    int total = NKP * NPAD;
    if (idx < 3 * total) {
        int l = idx / total;
        int r = idx - l * total;
        int kp = r / NPAD, n = r - kp * NPAD;
        const float* W = (l == 0) ? W1 : (l == 1) ? W2 : W3;
        int k0 = 2 * kp, k1 = 2 * kp + 1;
        float w0 = (k0 < EMB && n < EMB) ? W[k0 * EMB + n] : 0.f;
        float w1 = (k1 < EMB && n < EMB) ? W[k1 * EMB + n] : 0.f;
        __half h0 = __float2half_rn(w0);
        __half h1 = __float2half_rn(w1);
        __half l0 = __float2half_rn(w0 - __half2float(h0));
        __half l1 = __float2half_rn(w1 - __half2float(h1));
        g_Whi[l][r] = pack_h2(h0, h1);
        g_Wlo[l][r] = pack_h2(l0, l1);
    }
}

// ---------------- B: ELL scatter (4 edges/thread, atomic bump) -------------
__global__ void ell_scatter_kernel(const void* ei) {
    int t = blockIdx.x * blockDim.x + threadIdx.x;
    int e0 = t * 4;
    if (e0 >= N_EDGES) return;
    int s[4], d[4];
    if (g_flag_ei) {
        const longlong2* ps = (const longlong2*)ei + e0 / 2;
        const longlong2* pd = (const longlong2*)ei + (N_EDGES + e0) / 2;
        longlong2 a = __ldg(ps), b = __ldg(ps + 1);
        longlong2 c = __ldg(pd), e = __ldg(pd + 1);
        s[0] = (int)a.x; s[1] = (int)a.y; s[2] = (int)b.x; s[3] = (int)b.y;
        d[0] = (int)c.x; d[1] = (int)c.y; d[2] = (int)e.x; d[3] = (int)e.y;
    } else {
        int4 a = __ldg((const int4*)((const int*)ei + e0));
        int4 b = __ldg((const int4*)((const int*)ei + N_EDGES + e0));
        s[0] = a.x; s[1] = a.y; s[2] = a.z; s[3] = a.w;
        d[0] = b.x; d[1] = b.y; d[2] = b.z; d[3] = b.w;
    }
#pragma unroll
    for (int q = 0; q < 4; q++) {
        int p = atomicAdd(&g_cur[d[q]], 1);
        if (p < ELLW) g_esrc[(size_t)d[q] * ELLW + p] = s[q];
    }
}

// ---------------- C: finalize (dinv + ELL coefs + graph boundaries) --------
__global__ void finalize_kernel(const void* bi) {
    int i = blockIdx.x * blockDim.x + threadIdx.x;
    if (i >= N_NODES) return;
    int deg = g_cur[i];
    if (deg > ELLW) deg = ELLW;
    float di = rsqrtf((float)(g_cur[i] + 1));
    g_dinv[i] = di;
    const int* es = g_esrc + (size_t)i * ELLW;
    int2* el = g_ell + (size_t)i * ELLW;
    for (int j = 0; j < deg; j++) {
        int s = es[j];
        float ds = rsqrtf((float)(__ldg(&g_cur[s]) + 1));
        el[j] = make_int2(s, __float_as_int(ds * di));
    }
    // graph boundary detection on sorted batch_index
    int is64 = g_flag_bi;
    int b = ld_idx(bi, i, is64);
    if (i == 0) {
        for (int g = 0; g <= b; g++) g_goff[g] = 0;
    }
    if (i == N_NODES - 1) {
        for (int g = b + 1; g <= N_GRAPHS; g++) g_goff[g] = N_NODES;
    } else {
        int bn = ld_idx(bi, i + 1, is64);
        for (int g = b + 1; g <= bn; g++) g_goff[g] = i + 1;
    }
}

// ---------------- layer 0 (split): aggregate4 then gemm0f ------------------
__global__ void aggregate4_kernel(const float* __restrict__ x,
                                  float* __restrict__ outx) {
    int i = blockIdx.x * blockDim.x + threadIdx.x;
    if (i >= N_NODES) return;
    int deg = g_cur[i];
    if (deg > ELLW) deg = ELLW;
    float dv = g_dinv[i];
    float selfc = dv * dv;
    float4 xi = *reinterpret_cast<const float4*>(x + (size_t)i * 4);
    float4 a = make_float4(selfc * xi.x, selfc * xi.y, selfc * xi.z, selfc * xi.w);
    const int2* el = g_ell + (size_t)i * ELLW;
    for (int e = 0; e < deg; e++) {
        int2 sc = __ldg(&el[e]);
        float c = __int_as_float(sc.y);
        float4 v = *reinterpret_cast<const float4*>(x + (size_t)sc.x * 4);
        a.x += c * v.x; a.y += c * v.y; a.z += c * v.z; a.w += c * v.w;
    }
    *reinterpret_cast<float4*>(outx + (size_t)i * 4) = a;
}

// thread per output PAIR; coalesced W0 reads; writes fp16
__global__ void gemm0f_kernel(const float* __restrict__ xa,
                              const float* __restrict__ W0,
                              const float* __restrict__ b0,
                              __half* __restrict__ out) {
    int idx = blockIdx.x * blockDim.x + threadIdx.x;
    if (idx >= N_NODES * (EMB / 2)) return;
    int i = idx / (EMB / 2), p = idx - i * (EMB / 2);
    int f0 = 2 * p;
    const float* xr = xa + (size_t)i * 4;
    float x0 = xr[0], x1 = xr[1], x2 = xr[2], x3 = xr[3];
    float s0 = x0 * __ldg(&W0[f0])
             + x1 * __ldg(&W0[EMB + f0])
             + x2 * __ldg(&W0[2 * EMB + f0])
             + x3 * __ldg(&W0[3 * EMB + f0])
             + __ldg(&b0[f0]);
    float s1 = x0 * __ldg(&W0[f0 + 1])
             + x1 * __ldg(&W0[EMB + f0 + 1])
             + x2 * __ldg(&W0[2 * EMB + f0 + 1])
             + x3 * __ldg(&W0[3 * EMB + f0 + 1])
             + __ldg(&b0[f0 + 1]);
    s0 = s0 > 0.f ? s0 : 0.01f * s0;
    s1 = s1 > 0.f ? s1 : 0.01f * s1;
    __half2 o = __floats2half2_rn(s0, s1);
    *reinterpret_cast<__half2*>(&out[(size_t)i * EMB + f0]) = o;
}

// ---------------- layers 1-3: fp16x2 split GEMM via mma.sync.m16n8k16 ------
#define GBM   64
#define ASTR  12
#define BSTR  216

#define MMA_F16(d, a0, a1, a2, a3, b0, b1)                                    \
    asm volatile("mma.sync.aligned.m16n8k16.row.col.f32.f16.f16.f32 "        \
                 "{%0,%1,%2,%3}, {%4,%5,%6,%7}, {%8,%9}, {%0,%1,%2,%3};"     \
                 : "+f"((d)[0]), "+f"((d)[1]), "+f"((d)[2]), "+f"((d)[3])    \
                 : "r"(a0), "r"(a1), "r"(a2), "r"(a3), "r"(b0), "r"(b1))

__global__ __launch_bounds__(128) void gemm_f16x2_kernel(
    const __half* __restrict__ h,
    const uint32_t* __restrict__ whi, const uint32_t* __restrict__ wlo,
    __half* __restrict__ out) {
    __shared__ uint32_t sA [2][GBM * ASTR];
    __shared__ uint32_t sBh[2][8 * BSTR];
    __shared__ uint32_t sBl[2][8 * BSTR];

    int tid  = threadIdx.x;
    int lane = tid & 31, warp = tid >> 5;
    int wm = warp >> 1;
    int wn = warp & 1;
    int row0 = blockIdx.x * GBM;
    int gid = lane >> 2;
    int tig = lane & 3;

    float acc[13][2][4];
#pragma unroll
    for (int t = 0; t < 13; t++)
#pragma unroll
        for (int f = 0; f < 2; f++) {
            acc[t][f][0] = 0.f; acc[t][f][1] = 0.f;
            acc[t][f][2] = 0.f; acc[t][f][3] = 0.f;
        }

    uint32_t ra[4];
    uint32_t rbh[13], rbl[13];

    auto FETCH = [&](int chunk) {
        int k0 = chunk * 16;
#pragma unroll
        for (int i = 0; i < 4; i++) {
            int idx = tid + i * 128;
            int r = idx >> 3, kp = idx & 7;
            int gr = row0 + r;
            int ka = k0 + 2 * kp;
            ra[i] = (gr < N_NODES && ka < EMB)
                  ? __ldg(reinterpret_cast<const uint32_t*>(h + (size_t)gr * EMB + ka))
                  : 0u;
        }
        int base = chunk * 8 * NPAD;
#pragma unroll
        for (int i = 0; i < 13; i++) {
            int idx = tid + i * 128;
            int r = idx / NPAD, c = idx - r * NPAD;
            int g = base + r * NPAD + c;
            rbh[i] = __ldg(&whi[g]);
            rbl[i] = __ldg(&wlo[g]);
        }
    };
    auto STORE = [&](int buf) {
#pragma unroll
        for (int i = 0; i < 4; i++) {
            int idx = tid + i * 128;
            int r = idx >> 3, kp = idx & 7;
            sA[buf][r * ASTR + kp] = ra[i];
        }
#pragma unroll
        for (int i = 0; i < 13; i++) {
            int idx = tid + i * 128;
            int r = idx / NPAD, c = idx - r * NPAD;
            sBh[buf][r * BSTR + c] = rbh[i];
            sBl[buf][r * BSTR + c] = rbl[i];
        }
    };

    FETCH(0);
    STORE(0);
    __syncthreads();

    int ar = wm * 32 + gid;
#pragma unroll 1
    for (int ks = 0; ks < 13; ks++) {
        int cur = ks & 1;
        if (ks < 12) FETCH(ks + 1);

        uint32_t a[8];
#pragma unroll
        for (int f = 0; f < 2; f++) {
            int r = ar + f * 16;
            a[f * 4 + 0] = sA[cur][r * ASTR + tig];
            a[f * 4 + 1] = sA[cur][(r + 8) * ASTR + tig];
            a[f * 4 + 2] = sA[cur][r * ASTR + tig + 4];
            a[f * 4 + 3] = sA[cur][(r + 8) * ASTR + tig + 4];
        }

#pragma unroll
        for (int t = 0; t < 13; t++) {
            int n = wn * 104 + t * 8 + gid;
            uint32_t bh0 = sBh[cur][tig * BSTR + n];
            uint32_t bh1 = sBh[cur][(tig + 4) * BSTR + n];
            uint32_t bl0 = sBl[cur][tig * BSTR + n];
            uint32_t bl1 = sBl[cur][(tig + 4) * BSTR + n];
            MMA_F16(acc[t][0], a[0], a[1], a[2], a[3], bh0, bh1);
            MMA_F16(acc[t][1], a[4], a[5], a[6], a[7], bh0, bh1);
            MMA_F16(acc[t][0], a[0], a[1], a[2], a[3], bl0, bl1);
            MMA_F16(acc[t][1], a[4], a[5], a[6], a[7], bl0, bl1);
        }

        if (ks < 12) STORE(cur ^ 1);
        __syncthreads();
    }

#pragma unroll
    for (int t = 0; t < 13; t++) {
        int n = wn * 104 + t * 8 + 2 * tig;
        if (n >= EMB) continue;
#pragma unroll
        for (int f = 0; f < 2; f++) {
            int r = row0 + wm * 32 + f * 16 + gid;
            if (r < N_NODES) {
                __half2 v = __floats2half2_rn(acc[t][f][0], acc[t][f][1]);
                *reinterpret_cast<__half2*>(&out[(size_t)r * EMB + n]) = v;
            }
            if (r + 8 < N_NODES) {
                __half2 v = __floats2half2_rn(acc[t][f][2], acc[t][f][3]);
                *reinterpret_cast<__half2*>(&out[(size_t)(r + 8) * EMB + n]) = v;
            }
        }
    }
}

// ---------------- edge aggregation (fp16 gather, warp per dst node) --------
__device__ __forceinline__ void unpack8(uint4 v, float* f) {
    float2 t;
    t = __half22float2(*reinterpret_cast<__half2*>(&v.x)); f[0] = t.x; f[1] = t.y;
    t = __half22float2(*reinterpret_cast<__half2*>(&v.y)); f[2] = t.x; f[3] = t.y;
    t = __half22float2(*reinterpret_cast<__half2*>(&v.z)); f[4] = t.x; f[5] = t.y;
    t = __half22float2(*reinterpret_cast<__half2*>(&v.w)); f[6] = t.x; f[7] = t.y;
}

__global__ __launch_bounds__(256) void aggregate_h_kernel(
    const __half* __restrict__ hw, const float* __restrict__ b,
    __half* __restrict__ out) {
    int warp = (blockIdx.x * blockDim.x + threadIdx.x) >> 5;
    int lane = threadIdx.x & 31;
    if (warp >= N_NODES || lane >= 25) return;
    int i = warp;

    int deg = g_cur[i];
    if (deg > ELLW) deg = ELLW;
    float dv = g_dinv[i];
    float selfc = dv * dv;

    const uint4* h4 = reinterpret_cast<const uint4*>(hw);
    float acc[8], f[8];
    {
        uint4 v = __ldg(&h4[(size_t)i * 25 + lane]);
        unpack8(v, f);
#pragma unroll
        for (int j = 0; j < 8; j++) acc[j] = selfc * f[j];
    }

    const int2* el = g_ell + (size_t)i * ELLW;
    for (int e = 0; e < deg; e++) {
        int2 sc = __ldg(&el[e]);
        int   s = sc.x;
        float c = __int_as_float(sc.y);
        uint4 v = __ldg(&h4[(size_t)s * 25 + lane]);
        unpack8(v, f);
#pragma unroll
        for (int j = 0; j < 8; j++) acc[j] += c * f[j];
    }

    int f0 = lane * 8;
    float4 b0 = *reinterpret_cast<const float4*>(b + f0);
    float4 b1 = *reinterpret_cast<const float4*>(b + f0 + 4);
    acc[0] += b0.x; acc[1] += b0.y; acc[2] += b0.z; acc[3] += b0.w;
    acc[4] += b1.x; acc[5] += b1.y; acc[6] += b1.z; acc[7] += b1.w;
#pragma unroll
    for (int j = 0; j < 8; j++) acc[j] = acc[j] > 0.f ? acc[j] : 0.01f * acc[j];

    uint4 pv;
    __half2 p;
    p = __floats2half2_rn(acc[0], acc[1]); pv.x = *reinterpret_cast<uint32_t*>(&p);
    p = __floats2half2_rn(acc[2], acc[3]); pv.y = *reinterpret_cast<uint32_t*>(&p);
    p = __floats2half2_rn(acc[4], acc[5]); pv.z = *reinterpret_cast<uint32_t*>(&p);
    p = __floats2half2_rn(acc[6], acc[7]); pv.w = *reinterpret_cast<uint32_t*>(&p);
    reinterpret_cast<uint4*>(out)[(size_t)i * 25 + lane] = pv;
}

// ---------------- pooling + MLP head (fused, block per graph) --------------
__global__ __launch_bounds__(256) void poolmlp_kernel(
    const __half* __restrict__ h, const float* __restrict__ xs,
    const float* __restrict__ Wl1, const float* __restrict__ bl1,
    const float* __restrict__ Wl2, const float* __restrict__ bl2,
    float* __restrict__ out) {
    int g = blockIdx.x;
    int t = threadIdx.x;
    __shared__ float gv[EMB + N_FEAT];
    __shared__ float red[HID];

    int r0 = g_goff[g];
    int n  = g_goff[g + 1] - r0;
    if (t < EMB) {
        float s = 0.f;
        for (int j = 0; j < n; j++) s += __half2float(h[(size_t)(r0 + j) * EMB + t]);
        gv[t] = s / fmaxf((float)n, 1.0f);
    } else if (t < EMB + N_FEAT) {
        gv[t] = xs[g * N_FEAT + (t - EMB)];
    }
    __syncthreads();

    if (t < HID) {
        float acc = bl1[t];
        for (int k = 0; k < EMB + N_FEAT; k++) acc += gv[k] * Wl1[k * HID + t];
        acc = acc > 0.f ? acc : 0.01f * acc;
        red[t] = acc * Wl2[t];
    }
    __syncthreads();
    for (int s = HID / 2; s > 0; s >>= 1) {
        if (t < s) red[t] += red[t + s];
        __syncthreads();
    }
    if (t == 0) out[g] = red[0] + bl2[0];
}

// ---------------- launcher --------------------------------------------------
extern "C" void kernel_launch(void* const* d_in, const int* in_sizes, int n_in,
                              void* d_out, int out_size) {
    const float* x        = (const float*)d_in[0];
    const void*  ei       = d_in[1];
    const float* x_scalar = (const float*)d_in[2];
    const void*  bi       = d_in[3];
    const float* W0  = (const float*)d_in[4];
    const float* b0  = (const float*)d_in[5];
    const float* W1  = (const float*)d_in[6];
    const float* b1  = (const float*)d_in[7];
    const float* W2  = (const float*)d_in[8];
    const float* b2  = (const float*)d_in[9];
    const float* W3  = (const float*)d_in[10];
    const float* b3  = (const float*)d_in[11];
    const float* Wl1 = (const float*)d_in[12];
    const float* bl1 = (const float*)d_in[13];
    const float* Wl2 = (const float*)d_in[14];
    const float* bl2 = (const float*)d_in[15];
    float* out = (float*)d_out;

    __half *bufA, *bufB, *hw;
    float* aggx;
    uint32_t *whi, *wlo;
    cudaGetSymbolAddress((void**)&bufA, g_bufA);
    cudaGetSymbolAddress((void**)&bufB, g_bufB);
    cudaGetSymbolAddress((void**)&hw,   g_hw);
    cudaGetSymbolAddress((void**)&aggx, g_aggx);
    cudaGetSymbolAddress((void**)&whi,  g_Whi);
    cudaGetSymbolAddress((void**)&wlo,  g_Wlo);

    const int TB = 256;
    int splitTot = 3 * NKP * NPAD;                       // 64896
    int gridA  = (splitTot + TB - 1) / TB;               // covers N_NODES too
    int gridB  = (N_EDGES / 4 + TB - 1) / TB;            // 391
    int gridC  = (N_NODES + TB - 1) / TB;                // 196
    int gridG0 = (N_NODES * (EMB / 2) + TB - 1) / TB;
    int gridD  = (N_NODES * 32 + TB - 1) / TB;           // 6250 (warp/node)
    int gridGm = (N_NODES + GBM - 1) / GBM;              // 782

    const int WTOT = NKP * NPAD;

    // preprocessing (3 launches)
    init_split_kernel<<<gridA, TB>>>(ei, bi, W1, W2, W3);
    ell_scatter_kernel<<<gridB, TB>>>(ei);
    finalize_kernel<<<gridC, TB>>>(bi);

    // layer 0 (split: aggregate-first by linearity, then coalesced gemm0)
    aggregate4_kernel<<<gridC, TB>>>(x, aggx);
    gemm0f_kernel<<<gridG0, TB>>>(aggx, W0, b0, bufA);

    // layer 1
    gemm_f16x2_kernel<<<gridGm, 128>>>(bufA, whi, wlo, hw);
    aggregate_h_kernel<<<gridD, TB>>>(hw, b1, bufB);
    // layer 2
    gemm_f16x2_kernel<<<gridGm, 128>>>(bufB, whi + WTOT, wlo + WTOT, hw);
    aggregate_h_kernel<<<gridD, TB>>>(hw, b2, bufA);
    // layer 3
    gemm_f16x2_kernel<<<gridGm, 128>>>(bufA, whi + 2 * WTOT, wlo + 2 * WTOT, hw);
    aggregate_h_kernel<<<gridD, TB>>>(hw, b3, bufB);

    // pool + MLP head (fused)
    poolmlp_kernel<<<N_GRAPHS, TB>>>(bufB, x_scalar, Wl1, bl1, Wl2, bl2, out);
}

// round 16
// speedup vs baseline: 1.1813x; 1.0586x over previous
#include <cuda_runtime.h>
#include <cuda_fp16.h>
#include <cstdint>

#define N_NODES  50000
#define N_EDGES  400000
#define N_GRAPHS 500
#define N_FEAT   4
#define EMB      200
#define HID      128

// padded GEMM dims
#define KPAD 208            // K padded (13 chunks of 16)
#define NPAD 208            // N padded
#define NKP  (KPAD / 2)     // 104 k-pairs

// ---------------- device scratch (no runtime allocation allowed) ----------
__device__ __half g_bufA[(size_t)N_NODES * EMB];
__device__ __half g_bufB[(size_t)N_NODES * EMB];
__device__ __half g_hw  [(size_t)N_NODES * EMB];
__device__ float  g_aggx[(size_t)N_NODES * 4];
__device__ float g_dinv[N_NODES];
__device__ int   g_deg [N_NODES];
__device__ int   g_off [N_NODES + 1];
__device__ int   g_cur [N_NODES];
__device__ int2  g_csr [N_EDGES];       // {src, coef bits} packed
__device__ int   g_flag_ei;
__device__ int   g_flag_bi;
__device__ int   g_goff[N_GRAPHS + 1];  // node offsets per graph (sorted batch)
__device__ int   g_part [64];
__device__ int   g_pscan[64];
// packed fp16 hi/lo splits of W1..W3: [layer][kpair][n] as (f16 k, f16 k+1)
__device__ uint32_t g_Whi[3][NKP * NPAD];
__device__ uint32_t g_Wlo[3][NKP * NPAD];

__device__ __forceinline__ int ld_idx(const void* p, long long i, int is64) {
    if (is64) return (int)((const long long*)p)[i];
    return ((const int*)p)[i];
}

// ---------------- init + dtype detection (fused) ---------------------------
__global__ void init_kernel(const void* ei, const void* bi) {
    int i = blockIdx.x * blockDim.x + threadIdx.x;
    if (i < N_NODES) { g_deg[i] = 0; g_cur[i] = 0; }
    if (i == 0) {
        const int* e32 = (const int*)ei;
        int all0 = 1;
        for (int k = 0; k < 16; k++) if (e32[2 * k + 1] != 0) all0 = 0;
        g_flag_ei = all0;
        const int* b32 = (const int*)bi;
        int all0b = 1;
        for (int k = 0; k < 16; k++) if (b32[2 * (20000 + k) + 1] != 0) all0b = 0;
        g_flag_bi = all0b;
    }
}

// ---------------- fused: degree histogram (4 edges/thr, vectorized) --------
// + graph boundary detection on sorted batch_index
__global__ void count_kernel(const void* ei, const void* bi) {
    int t = blockIdx.x * blockDim.x + threadIdx.x;
    int e0 = t * 4;
    if (e0 < N_EDGES) {
        int d0, d1, d2, d3;
        if (g_flag_ei) {
            const longlong2* p = (const longlong2*)ei + (N_EDGES + e0) / 2;
            longlong2 a = __ldg(p), b = __ldg(p + 1);
            d0 = (int)a.x; d1 = (int)a.y; d2 = (int)b.x; d3 = (int)b.y;
        } else {
            int4 a = __ldg((const int4*)((const int*)ei + N_EDGES + e0));
            d0 = a.x; d1 = a.y; d2 = a.z; d3 = a.w;
        }
        atomicAdd(&g_deg[d0], 1); atomicAdd(&g_deg[d1], 1);
        atomicAdd(&g_deg[d2], 1); atomicAdd(&g_deg[d3], 1);
    }
    int i = t;
    if (i < N_NODES) {
        int is64 = g_flag_bi;
        int b = ld_idx(bi, i, is64);
        if (i == 0) {
            for (int g = 0; g <= b; g++) g_goff[g] = 0;
        }
        if (i == N_NODES - 1) {
            for (int g = b + 1; g <= N_GRAPHS; g++) g_goff[g] = N_NODES;
        } else {
            int bn = ld_idx(bi, i + 1, is64);
            for (int g = b + 1; g <= bn; g++) g_goff[g] = i + 1;
        }
    }
}

#define SCAN_B 1024
#define SCAN_NB ((N_NODES + SCAN_B - 1) / SCAN_B)   // 49

__global__ void scan_part_kernel() {
    __shared__ int ws[32];
    int i = blockIdx.x * SCAN_B + threadIdx.x;
    int v = (i < N_NODES) ? g_deg[i] : 0;
#pragma unroll
    for (int d = 16; d; d >>= 1) v += __shfl_down_sync(0xffffffffu, v, d);
    if ((threadIdx.x & 31) == 0) ws[threadIdx.x >> 5] = v;
    __syncthreads();
    if (threadIdx.x < 32) {
        int s = ws[threadIdx.x];
#pragma unroll
        for (int d = 16; d; d >>= 1) s += __shfl_down_sync(0xffffffffu, s, d);
        if (threadIdx.x == 0) g_part[blockIdx.x] = s;
    }
}

__global__ void scan_top_kernel() {
    __shared__ int s[64];
    int t = threadIdx.x;   // 64 threads
    int v = (t < SCAN_NB) ? g_part[t] : 0;
    s[t] = v;
    __syncthreads();
    for (int d = 1; d < 64; d <<= 1) {
        int u = 0;
        if (t >= d) u = s[t - d];
        __syncthreads();
        s[t] += u;
        __syncthreads();
    }
    if (t < SCAN_NB) g_pscan[t] = s[t] - v;
    if (t == 0) g_off[N_NODES] = N_EDGES;
}

__global__ void scan_final_kernel() {
    __shared__ int wsum[32];
    int tid = threadIdx.x, lane = tid & 31, wid = tid >> 5;
    int i = blockIdx.x * SCAN_B + tid;
    int v = (i < N_NODES) ? g_deg[i] : 0;
    int inc = v;
#pragma unroll
    for (int d = 1; d < 32; d <<= 1) {
        int u = __shfl_up_sync(0xffffffffu, inc, d);
        if (lane >= d) inc += u;
    }
    if (lane == 31) wsum[wid] = inc;
    __syncthreads();
    if (wid == 0) {
        int s = wsum[lane];
        int si = s;
#pragma unroll
        for (int d = 1; d < 32; d <<= 1) {
            int u = __shfl_up_sync(0xffffffffu, si, d);
            if (lane >= d) si += u;
        }
        wsum[lane] = si - s;
    }
    __syncthreads();
    if (i < N_NODES) {
        g_off[i]  = g_pscan[blockIdx.x] + wsum[wid] + (inc - v);
        g_dinv[i] = rsqrtf((float)(v + 1));
    }
}

// 2 edges per thread, vectorized loads, packed 8B CSR stores
__global__ void scatter_kernel(const void* ei) {
    int t = blockIdx.x * blockDim.x + threadIdx.x;
    int e0 = t * 2;
    if (e0 >= N_EDGES) return;
    int s0, s1, d0, d1;
    if (g_flag_ei) {
        longlong2 sv = __ldg((const longlong2*)ei + e0 / 2);
        longlong2 dv = __ldg((const longlong2*)ei + (N_EDGES + e0) / 2);
        s0 = (int)sv.x; s1 = (int)sv.y; d0 = (int)dv.x; d1 = (int)dv.y;
    } else {
        int2 sv = __ldg((const int2*)((const int*)ei + e0));
        int2 dv = __ldg((const int2*)((const int*)ei + N_EDGES + e0));
        s0 = sv.x; s1 = sv.y; d0 = dv.x; d1 = dv.y;
    }
    int p0 = g_off[d0] + atomicAdd(&g_cur[d0], 1);
    g_csr[p0] = make_int2(s0, __float_as_int(g_dinv[s0] * g_dinv[d0]));
    int p1 = g_off[d1] + atomicAdd(&g_cur[d1], 1);
    g_csr[p1] = make_int2(s1, __float_as_int(g_dinv[s1] * g_dinv[d1]));
}

// ---------------- W split precompute (fp16 hi/lo) --------------------------
__device__ __forceinline__ uint32_t pack_h2(__half lo, __half hi) {
    uint16_t a = __half_as_ushort(lo);
    uint16_t b = __half_as_ushort(hi);
    return (uint32_t)a | ((uint32_t)b << 16);
}

__global__ void split_w_kernel(const float* __restrict__ W1,
                               const float* __restrict__ W2,
                               const float* __restrict__ W3) {
    int idx = blockIdx.x * blockDim.x + threadIdx.x;
    int total = NKP * NPAD;
    if (idx >= 3 * total) return;
    int l = idx / total;
    int r = idx - l * total;
    int kp = r / NPAD, n = r - kp * NPAD;
    const float* W = (l == 0) ? W1 : (l == 1) ? W2 : W3;
    int k0 = 2 * kp, k1 = 2 * kp + 1;
    float w0 = (k0 < EMB && n < EMB) ? W[k0 * EMB + n] : 0.f;
    float w1 = (k1 < EMB && n < EMB) ? W[k1 * EMB + n] : 0.f;
    __half h0 = __float2half_rn(w0);
    __half h1 = __float2half_rn(w1);
    __half l0 = __float2half_rn(w0 - __half2float(h0));
    __half l1 = __float2half_rn(w1 - __half2float(h1));
    g_Whi[l][r] = pack_h2(h0, h1);   // low 16 bits = even k
    g_Wlo[l][r] = pack_h2(l0, l1);
}

// ---------------- layer 0: aggregate(x) with 4 threads/node ----------------
// sub-warp gather (4-way MLP) + shfl_xor reduce within the aligned 4-group.
__global__ void aggregate4_kernel(const float* __restrict__ x,
                                  float* __restrict__ outx) {
    int t = blockIdx.x * blockDim.x + threadIdx.x;
    int i = t >> 2;
    int sub = t & 3;
    if (i >= N_NODES) return;
    float ax = 0.f, ay = 0.f, az = 0.f, aw = 0.f;
    if (sub == 0) {
        float dv = g_dinv[i];
        float sc = dv * dv;
        float4 xi = *reinterpret_cast<const float4*>(x + (size_t)i * 4);
        ax = sc * xi.x; ay = sc * xi.y; az = sc * xi.z; aw = sc * xi.w;
    }
    int e0 = g_off[i], e1 = g_off[i + 1];
    for (int e = e0 + sub; e < e1; e += 4) {
        int2 sc2 = __ldg(&g_csr[e]);
        float c = __int_as_float(sc2.y);
        float4 v = *reinterpret_cast<const float4*>(x + (size_t)sc2.x * 4);
        ax += c * v.x; ay += c * v.y; az += c * v.z; aw += c * v.w;
    }
#pragma unroll
    for (int d = 1; d < 4; d <<= 1) {
        ax += __shfl_xor_sync(0xffffffffu, ax, d);
        ay += __shfl_xor_sync(0xffffffffu, ay, d);
        az += __shfl_xor_sync(0xffffffffu, az, d);
        aw += __shfl_xor_sync(0xffffffffu, aw, d);
    }
    if (sub == 0)
        *reinterpret_cast<float4*>(outx + (size_t)i * 4) =
            make_float4(ax, ay, az, aw);
}

// thread per output PAIR; coalesced W0 reads; writes fp16
__global__ void gemm0f_kernel(const float* __restrict__ xa,
                              const float* __restrict__ W0,
                              const float* __restrict__ b0,
                              __half* __restrict__ out) {
    int idx = blockIdx.x * blockDim.x + threadIdx.x;
    if (idx >= N_NODES * (EMB / 2)) return;
    int i = idx / (EMB / 2), p = idx - i * (EMB / 2);
    int f0 = 2 * p;
    const float* xr = xa + (size_t)i * 4;
    float x0 = xr[0], x1 = xr[1], x2 = xr[2], x3 = xr[3];
    float s0 = x0 * __ldg(&W0[f0])
             + x1 * __ldg(&W0[EMB + f0])
             + x2 * __ldg(&W0[2 * EMB + f0])
             + x3 * __ldg(&W0[3 * EMB + f0])
             + __ldg(&b0[f0]);
    float s1 = x0 * __ldg(&W0[f0 + 1])
             + x1 * __ldg(&W0[EMB + f0 + 1])
             + x2 * __ldg(&W0[2 * EMB + f0 + 1])
             + x3 * __ldg(&W0[3 * EMB + f0 + 1])
             + __ldg(&b0[f0 + 1]);
    s0 = s0 > 0.f ? s0 : 0.01f * s0;
    s1 = s1 > 0.f ? s1 : 0.01f * s1;
    __half2 o = __floats2half2_rn(s0, s1);
    *reinterpret_cast<__half2*>(&out[(size_t)i * EMB + f0]) = o;
}

// ---------------- layers 1-3: fp16x2 split GEMM via mma.sync.m16n8k16 ------
#define GBM   64
#define ASTR  12
#define BSTR  216

#define MMA_F16(d, a0, a1, a2, a3, b0, b1)                                    \
    asm volatile("mma.sync.aligned.m16n8k16.row.col.f32.f16.f16.f32 "        \
                 "{%0,%1,%2,%3}, {%4,%5,%6,%7}, {%8,%9}, {%0,%1,%2,%3};"     \
                 : "+f"((d)[0]), "+f"((d)[1]), "+f"((d)[2]), "+f"((d)[3])    \
                 : "r"(a0), "r"(a1), "r"(a2), "r"(a3), "r"(b0), "r"(b1))

__global__ __launch_bounds__(128) void gemm_f16x2_kernel(
    const __half* __restrict__ h,
    const uint32_t* __restrict__ whi, const uint32_t* __restrict__ wlo,
    __half* __restrict__ out) {
    __shared__ uint32_t sA [2][GBM * ASTR];
    __shared__ uint32_t sBh[2][8 * BSTR];
    __shared__ uint32_t sBl[2][8 * BSTR];

    int tid  = threadIdx.x;
    int lane = tid & 31, warp = tid >> 5;
    int wm = warp >> 1;
    int wn = warp & 1;
    int row0 = blockIdx.x * GBM;
    int gid = lane >> 2;
    int tig = lane & 3;

    float acc[13][2][4];
#pragma unroll
    for (int t = 0; t < 13; t++)
#pragma unroll
        for (int f = 0; f < 2; f++) {
            acc[t][f][0] = 0.f; acc[t][f][1] = 0.f;
            acc[t][f][2] = 0.f; acc[t][f][3] = 0.f;
        }

    uint32_t ra[4];
    uint32_t rbh[13], rbl[13];

    auto FETCH = [&](int chunk) {
        int k0 = chunk * 16;
#pragma unroll
        for (int i = 0; i < 4; i++) {
            int idx = tid + i * 128;
            int r = idx >> 3, kp = idx & 7;
            int gr = row0 + r;
            int ka = k0 + 2 * kp;
            ra[i] = (gr < N_NODES && ka < EMB)
                  ? __ldg(reinterpret_cast<const uint32_t*>(h + (size_t)gr * EMB + ka))
                  : 0u;
        }
        int base = chunk * 8 * NPAD;
#pragma unroll
        for (int i = 0; i < 13; i++) {
            int idx = tid + i * 128;
            int r = idx / NPAD, c = idx - r * NPAD;
            int g = base + r * NPAD + c;
            rbh[i] = __ldg(&whi[g]);
            rbl[i] = __ldg(&wlo[g]);
        }
    };
    auto STORE = [&](int buf) {
#pragma unroll
        for (int i = 0; i < 4; i++) {
            int idx = tid + i * 128;
            int r = idx >> 3, kp = idx & 7;
            sA[buf][r * ASTR + kp] = ra[i];
        }
#pragma unroll
        for (int i = 0; i < 13; i++) {
            int idx = tid + i * 128;
            int r = idx / NPAD, c = idx - r * NPAD;
            sBh[buf][r * BSTR + c] = rbh[i];
            sBl[buf][r * BSTR + c] = rbl[i];
        }
    };

    FETCH(0);
    STORE(0);
    __syncthreads();

    int ar = wm * 32 + gid;
#pragma unroll 1
    for (int ks = 0; ks < 13; ks++) {
        int cur = ks & 1;
        if (ks < 12) FETCH(ks + 1);

        uint32_t a[8];
#pragma unroll
        for (int f = 0; f < 2; f++) {
            int r = ar + f * 16;
            a[f * 4 + 0] = sA[cur][r * ASTR + tig];
            a[f * 4 + 1] = sA[cur][(r + 8) * ASTR + tig];
            a[f * 4 + 2] = sA[cur][r * ASTR + tig + 4];
            a[f * 4 + 3] = sA[cur][(r + 8) * ASTR + tig + 4];
        }

#pragma unroll
        for (int t = 0; t < 13; t++) {
            int n = wn * 104 + t * 8 + gid;
            uint32_t bh0 = sBh[cur][tig * BSTR + n];
            uint32_t bh1 = sBh[cur][(tig + 4) * BSTR + n];
            uint32_t bl0 = sBl[cur][tig * BSTR + n];
            uint32_t bl1 = sBl[cur][(tig + 4) * BSTR + n];
            MMA_F16(acc[t][0], a[0], a[1], a[2], a[3], bh0, bh1);
            MMA_F16(acc[t][1], a[4], a[5], a[6], a[7], bh0, bh1);
            MMA_F16(acc[t][0], a[0], a[1], a[2], a[3], bl0, bl1);
            MMA_F16(acc[t][1], a[4], a[5], a[6], a[7], bl0, bl1);
        }

        if (ks < 12) STORE(cur ^ 1);
        __syncthreads();
    }

#pragma unroll
    for (int t = 0; t < 13; t++) {
        int n = wn * 104 + t * 8 + 2 * tig;
        if (n >= EMB) continue;
#pragma unroll
        for (int f = 0; f < 2; f++) {
            int r = row0 + wm * 32 + f * 16 + gid;
            if (r < N_NODES) {
                __half2 v = __floats2half2_rn(acc[t][f][0], acc[t][f][1]);
                *reinterpret_cast<__half2*>(&out[(size_t)r * EMB + n]) = v;
            }
            if (r + 8 < N_NODES) {
                __half2 v = __floats2half2_rn(acc[t][f][2], acc[t][f][3]);
                *reinterpret_cast<__half2*>(&out[(size_t)(r + 8) * EMB + n]) = v;
            }
        }
    }
}

// ---------------- edge aggregation (fp16 gather, warp per dst node) --------
__device__ __forceinline__ void unpack8(uint4 v, float* f) {
    float2 t;
    t = __half22float2(*reinterpret_cast<__half2*>(&v.x)); f[0] = t.x; f[1] = t.y;
    t = __half22float2(*reinterpret_cast<__half2*>(&v.y)); f[2] = t.x; f[3] = t.y;
    t = __half22float2(*reinterpret_cast<__half2*>(&v.z)); f[4] = t.x; f[5] = t.y;
    t = __half22float2(*reinterpret_cast<__half2*>(&v.w)); f[6] = t.x; f[7] = t.y;
}

__global__ __launch_bounds__(256) void aggregate_h_kernel(
    const __half* __restrict__ hw, const float* __restrict__ b,
    __half* __restrict__ out) {
    int warp = (blockIdx.x * blockDim.x + threadIdx.x) >> 5;
    int lane = threadIdx.x & 31;
    if (warp >= N_NODES || lane >= 25) return;
    int i = warp;

    float dv = g_dinv[i];
    float selfc = dv * dv;

    const uint4* h4 = reinterpret_cast<const uint4*>(hw);
    float acc[8], f[8];
    {
        uint4 v = __ldg(&h4[(size_t)i * 25 + lane]);
        unpack8(v, f);
#pragma unroll
        for (int j = 0; j < 8; j++) acc[j] = selfc * f[j];
    }

    int e0 = g_off[i], e1 = g_off[i + 1];
    for (int e = e0; e < e1; e++) {
        int2 sc = __ldg(&g_csr[e]);
        int   s = sc.x;
        float c = __int_as_float(sc.y);
        uint4 v = __ldg(&h4[(size_t)s * 25 + lane]);
        unpack8(v, f);
#pragma unroll
        for (int j = 0; j < 8; j++) acc[j] += c * f[j];
    }

    int f0 = lane * 8;
    float4 b0 = *reinterpret_cast<const float4*>(b + f0);
    float4 b1 = *reinterpret_cast<const float4*>(b + f0 + 4);
    acc[0] += b0.x; acc[1] += b0.y; acc[2] += b0.z; acc[3] += b0.w;
    acc[4] += b1.x; acc[5] += b1.y; acc[6] += b1.z; acc[7] += b1.w;
#pragma unroll
    for (int j = 0; j < 8; j++) acc[j] = acc[j] > 0.f ? acc[j] : 0.01f * acc[j];

    uint4 pv;
    __half2 p;
    p = __floats2half2_rn(acc[0], acc[1]); pv.x = *reinterpret_cast<uint32_t*>(&p);
    p = __floats2half2_rn(acc[2], acc[3]); pv.y = *reinterpret_cast<uint32_t*>(&p);
    p = __floats2half2_rn(acc[4], acc[5]); pv.z = *reinterpret_cast<uint32_t*>(&p);
    p = __floats2half2_rn(acc[6], acc[7]); pv.w = *reinterpret_cast<uint32_t*>(&p);
    reinterpret_cast<uint4*>(out)[(size_t)i * 25 + lane] = pv;
}

// ---------------- pooling + MLP head (fused, block per graph) --------------
__global__ __launch_bounds__(256) void poolmlp_kernel(
    const __half* __restrict__ h, const float* __restrict__ xs,
    const float* __restrict__ Wl1, const float* __restrict__ bl1,
    const float* __restrict__ Wl2, const float* __restrict__ bl2,
    float* __restrict__ out) {
    int g = blockIdx.x;
    int t = threadIdx.x;
    __shared__ float gv[EMB + N_FEAT];
    __shared__ float red[HID];

    int r0 = g_goff[g];
    int n  = g_goff[g + 1] - r0;
    if (t < EMB) {
        float s = 0.f;
        for (int j = 0; j < n; j++) s += __half2float(h[(size_t)(r0 + j) * EMB + t]);
        gv[t] = s / fmaxf((float)n, 1.0f);
    } else if (t < EMB + N_FEAT) {
        gv[t] = xs[g * N_FEAT + (t - EMB)];
    }
    __syncthreads();

    if (t < HID) {
        float acc = bl1[t];
        for (int k = 0; k < EMB + N_FEAT; k++) acc += gv[k] * Wl1[k * HID + t];
        acc = acc > 0.f ? acc : 0.01f * acc;
        red[t] = acc * Wl2[t];
    }
    __syncthreads();
    for (int s = HID / 2; s > 0; s >>= 1) {
        if (t < s) red[t] += red[t + s];
        __syncthreads();
    }
    if (t == 0) out[g] = red[0] + bl2[0];
}

// ---------------- launcher --------------------------------------------------
extern "C" void kernel_launch(void* const* d_in, const int* in_sizes, int n_in,
                              void* d_out, int out_size) {
    const float* x        = (const float*)d_in[0];
    const void*  ei       = d_in[1];
    const float* x_scalar = (const float*)d_in[2];
    const void*  bi       = d_in[3];
    const float* W0  = (const float*)d_in[4];
    const float* b0  = (const float*)d_in[5];
    const float* W1  = (const float*)d_in[6];
    const float* b1  = (const float*)d_in[7];
    const float* W2  = (const float*)d_in[8];
    const float* b2  = (const float*)d_in[9];
    const float* W3  = (const float*)d_in[10];
    const float* b3  = (const float*)d_in[11];
    const float* Wl1 = (const float*)d_in[12];
    const float* bl1 = (const float*)d_in[13];
    const float* Wl2 = (const float*)d_in[14];
    const float* bl2 = (const float*)d_in[15];
    float* out = (float*)d_out;

    __half *bufA, *bufB, *hw;
    float* aggx;
    uint32_t *whi, *wlo;
    cudaGetSymbolAddress((void**)&bufA, g_bufA);
    cudaGetSymbolAddress((void**)&bufB, g_bufB);
    cudaGetSymbolAddress((void**)&hw,   g_hw);
    cudaGetSymbolAddress((void**)&aggx, g_aggx);
    cudaGetSymbolAddress((void**)&whi,  g_Whi);
    cudaGetSymbolAddress((void**)&wlo,  g_Wlo);

    const int TB = 256;
    int gridN  = (N_NODES + TB - 1) / TB;
    int gridC  = (N_EDGES / 4 + TB - 1) / TB;          // 391 (also covers nodes)
    int gridS  = (N_EDGES / 2 + TB - 1) / TB;          // 782
    int gridA4 = (N_NODES * 4 + TB - 1) / TB;          // 782 (4 thr/node)
    int gridG0 = (N_NODES * (EMB / 2) + TB - 1) / TB;
    int gridAg = (N_NODES * 32 + TB - 1) / TB;
    int gridGm = (N_NODES + GBM - 1) / GBM;            // 782
    int gridW  = (3 * NKP * NPAD + TB - 1) / TB;

    // preprocessing (7 launches)
    init_kernel<<<gridN, TB>>>(ei, bi);
    split_w_kernel<<<gridW, TB>>>(W1, W2, W3);
    count_kernel<<<gridC, TB>>>(ei, bi);
    scan_part_kernel<<<SCAN_NB, SCAN_B>>>();
    scan_top_kernel<<<1, 64>>>();
    scan_final_kernel<<<SCAN_NB, SCAN_B>>>();
    scatter_kernel<<<gridS, TB>>>(ei);

    const int WTOT = NKP * NPAD;

    // layer 0 (aggregate-first by linearity; bias+leaky fused into gemm0f)
    aggregate4_kernel<<<gridA4, TB>>>(x, aggx);
    gemm0f_kernel<<<gridG0, TB>>>(aggx, W0, b0, bufA);

    // layer 1
    gemm_f16x2_kernel<<<gridGm, 128>>>(bufA, whi, wlo, hw);
    aggregate_h_kernel<<<gridAg, TB>>>(hw, b1, bufB);
    // layer 2
    gemm_f16x2_kernel<<<gridGm, 128>>>(bufB, whi + WTOT, wlo + WTOT, hw);
    aggregate_h_kernel<<<gridAg, TB>>>(hw, b2, bufA);
    // layer 3
    gemm_f16x2_kernel<<<gridGm, 128>>>(bufA, whi + 2 * WTOT, wlo + 2 * WTOT, hw);
    aggregate_h_kernel<<<gridAg, TB>>>(hw, b3, bufB);

    // pool + MLP head (fused)
    poolmlp_kernel<<<N_GRAPHS, TB>>>(bufB, x_scalar, Wl1, bl1, Wl2, bl2, out);
}

// round 17
// speedup vs baseline: 1.3895x; 1.1762x over previous
#include <cuda_runtime.h>
#include <cuda_fp16.h>
#include <cstdint>

#define N_NODES  50000
#define N_EDGES  400000
#define N_GRAPHS 500
#define N_FEAT   4
#define EMB      200
#define HID      128

// padded GEMM dims
#define KPAD 208            // K padded (13 chunks of 16)
#define NPAD 208            // N padded
#define NKP  (KPAD / 2)     // 104 k-pairs

// ---------------- device scratch (no runtime allocation allowed) ----------
__device__ __half g_bufA[(size_t)N_NODES * EMB];
__device__ __half g_bufB[(size_t)N_NODES * EMB];
__device__ __half g_hw  [(size_t)N_NODES * EMB];
__device__ float  g_aggx[(size_t)N_NODES * 4];
__device__ float g_dinv[N_NODES];
__device__ int   g_deg [N_NODES];
__device__ int   g_off [N_NODES + 1];
__device__ int   g_cur [N_NODES];
__device__ int2  g_csr [N_EDGES];       // {src, coef bits} packed
__device__ int   g_flag_ei;
__device__ int   g_flag_bi;
__device__ int   g_goff[N_GRAPHS + 1];  // node offsets per graph (sorted batch)
__device__ int   g_part [64];
__device__ int   g_pscan[64];
// packed fp16 of W1..W3: [layer][kpair][n] as (f16 k, f16 k+1)
__device__ uint32_t g_Whi[3][NKP * NPAD];

__device__ __forceinline__ int ld_idx(const void* p, long long i, int is64) {
    if (is64) return (int)((const long long*)p)[i];
    return ((const int*)p)[i];
}

// ---------------- init + dtype detection (fused) ---------------------------
__global__ void init_kernel(const void* ei, const void* bi) {
    int i = blockIdx.x * blockDim.x + threadIdx.x;
    if (i < N_NODES) { g_deg[i] = 0; g_cur[i] = 0; }
    if (i == 0) {
        const int* e32 = (const int*)ei;
        int all0 = 1;
        for (int k = 0; k < 16; k++) if (e32[2 * k + 1] != 0) all0 = 0;
        g_flag_ei = all0;
        const int* b32 = (const int*)bi;
        int all0b = 1;
        for (int k = 0; k < 16; k++) if (b32[2 * (20000 + k) + 1] != 0) all0b = 0;
        g_flag_bi = all0b;
    }
}

// ---------------- fused: degree histogram (4 edges/thr, vectorized) --------
// + graph boundary detection on sorted batch_index
__global__ void count_kernel(const void* ei, const void* bi) {
    int t = blockIdx.x * blockDim.x + threadIdx.x;
    int e0 = t * 4;
    if (e0 < N_EDGES) {
        int d0, d1, d2, d3;
        if (g_flag_ei) {
            const longlong2* p = (const longlong2*)ei + (N_EDGES + e0) / 2;
            longlong2 a = __ldg(p), b = __ldg(p + 1);
            d0 = (int)a.x; d1 = (int)a.y; d2 = (int)b.x; d3 = (int)b.y;
        } else {
            int4 a = __ldg((const int4*)((const int*)ei + N_EDGES + e0));
            d0 = a.x; d1 = a.y; d2 = a.z; d3 = a.w;
        }
        atomicAdd(&g_deg[d0], 1); atomicAdd(&g_deg[d1], 1);
        atomicAdd(&g_deg[d2], 1); atomicAdd(&g_deg[d3], 1);
    }
    int i = t;
    if (i < N_NODES) {
        int is64 = g_flag_bi;
        int b = ld_idx(bi, i, is64);
        if (i == 0) {
            for (int g = 0; g <= b; g++) g_goff[g] = 0;
        }
        if (i == N_NODES - 1) {
            for (int g = b + 1; g <= N_GRAPHS; g++) g_goff[g] = N_NODES;
        } else {
            int bn = ld_idx(bi, i + 1, is64);
            for (int g = b + 1; g <= bn; g++) g_goff[g] = i + 1;
        }
    }
}

#define SCAN_B 1024
#define SCAN_NB ((N_NODES + SCAN_B - 1) / SCAN_B)   // 49

__global__ void scan_part_kernel() {
    __shared__ int ws[32];
    int i = blockIdx.x * SCAN_B + threadIdx.x;
    int v = (i < N_NODES) ? g_deg[i] : 0;
#pragma unroll
    for (int d = 16; d; d >>= 1) v += __shfl_down_sync(0xffffffffu, v, d);
    if ((threadIdx.x & 31) == 0) ws[threadIdx.x >> 5] = v;
    __syncthreads();
    if (threadIdx.x < 32) {
        int s = ws[threadIdx.x];
#pragma unroll
        for (int d = 16; d; d >>= 1) s += __shfl_down_sync(0xffffffffu, s, d);
        if (threadIdx.x == 0) g_part[blockIdx.x] = s;
    }
}

__global__ void scan_top_kernel() {
    __shared__ int s[64];
    int t = threadIdx.x;   // 64 threads
    int v = (t < SCAN_NB) ? g_part[t] : 0;
    s[t] = v;
    __syncthreads();
    for (int d = 1; d < 64; d <<= 1) {
        int u = 0;
        if (t >= d) u = s[t - d];
        __syncthreads();
        s[t] += u;
        __syncthreads();
    }
    if (t < SCAN_NB) g_pscan[t] = s[t] - v;
    if (t == 0) g_off[N_NODES] = N_EDGES;
}

__global__ void scan_final_kernel() {
    __shared__ int wsum[32];
    int tid = threadIdx.x, lane = tid & 31, wid = tid >> 5;
    int i = blockIdx.x * SCAN_B + tid;
    int v = (i < N_NODES) ? g_deg[i] : 0;
    int inc = v;
#pragma unroll
    for (int d = 1; d < 32; d <<= 1) {
        int u = __shfl_up_sync(0xffffffffu, inc, d);
        if (lane >= d) inc += u;
    }
    if (lane == 31) wsum[wid] = inc;
    __syncthreads();
    if (wid == 0) {
        int s = wsum[lane];
        int si = s;
#pragma unroll
        for (int d = 1; d < 32; d <<= 1) {
            int u = __shfl_up_sync(0xffffffffu, si, d);
            if (lane >= d) si += u;
        }
        wsum[lane] = si - s;
    }
    __syncthreads();
    if (i < N_NODES) {
        g_off[i]  = g_pscan[blockIdx.x] + wsum[wid] + (inc - v);
        g_dinv[i] = rsqrtf((float)(v + 1));
    }
}

// 2 edges per thread, vectorized loads, packed 8B CSR stores
__global__ void scatter_kernel(const void* ei) {
    int t = blockIdx.x * blockDim.x + threadIdx.x;
    int e0 = t * 2;
    if (e0 >= N_EDGES) return;
    int s0, s1, d0, d1;
    if (g_flag_ei) {
        longlong2 sv = __ldg((const longlong2*)ei + e0 / 2);
        longlong2 dv = __ldg((const longlong2*)ei + (N_EDGES + e0) / 2);
        s0 = (int)sv.x; s1 = (int)sv.y; d0 = (int)dv.x; d1 = (int)dv.y;
    } else {
        int2 sv = __ldg((const int2*)((const int*)ei + e0));
        int2 dv = __ldg((const int2*)((const int*)ei + N_EDGES + e0));
        s0 = sv.x; s1 = sv.y; d0 = dv.x; d1 = dv.y;
    }
    int p0 = g_off[d0] + atomicAdd(&g_cur[d0], 1);
    g_csr[p0] = make_int2(s0, __float_as_int(g_dinv[s0] * g_dinv[d0]));
    int p1 = g_off[d1] + atomicAdd(&g_cur[d1], 1);
    g_csr[p1] = make_int2(s1, __float_as_int(g_dinv[s1] * g_dinv[d1]));
}

// ---------------- W precompute (fp16, packed pairs) -------------------------
__device__ __forceinline__ uint32_t pack_h2(__half lo, __half hi) {
    uint16_t a = __half_as_ushort(lo);
    uint16_t b = __half_as_ushort(hi);
    return (uint32_t)a | ((uint32_t)b << 16);
}

__global__ void split_w_kernel(const float* __restrict__ W1,
                               const float* __restrict__ W2,
                               const float* __restrict__ W3) {
    int idx = blockIdx.x * blockDim.x + threadIdx.x;
    int total = NKP * NPAD;
    if (idx >= 3 * total) return;
    int l = idx / total;
    int r = idx - l * total;
    int kp = r / NPAD, n = r - kp * NPAD;
    const float* W = (l == 0) ? W1 : (l == 1) ? W2 : W3;
    int k0 = 2 * kp, k1 = 2 * kp + 1;
    float w0 = (k0 < EMB && n < EMB) ? W[k0 * EMB + n] : 0.f;
    float w1 = (k1 < EMB && n < EMB) ? W[k1 * EMB + n] : 0.f;
    g_Whi[l][r] = pack_h2(__float2half_rn(w0), __float2half_rn(w1));
}

// ---------------- layer 0: aggregate(x) with 4 threads/node ----------------
__global__ void aggregate4_kernel(const float* __restrict__ x,
                                  float* __restrict__ outx) {
    int t = blockIdx.x * blockDim.x + threadIdx.x;
    int i = t >> 2;
    int sub = t & 3;
    if (i >= N_NODES) return;
    float ax = 0.f, ay = 0.f, az = 0.f, aw = 0.f;
    if (sub == 0) {
        float dv = g_dinv[i];
        float sc = dv * dv;
        float4 xi = *reinterpret_cast<const float4*>(x + (size_t)i * 4);
        ax = sc * xi.x; ay = sc * xi.y; az = sc * xi.z; aw = sc * xi.w;
    }
    int e0 = g_off[i], e1 = g_off[i + 1];
    for (int e = e0 + sub; e < e1; e += 4) {
        int2 sc2 = __ldg(&g_csr[e]);
        float c = __int_as_float(sc2.y);
        float4 v = *reinterpret_cast<const float4*>(x + (size_t)sc2.x * 4);
        ax += c * v.x; ay += c * v.y; az += c * v.z; aw += c * v.w;
    }
#pragma unroll
    for (int d = 1; d < 4; d <<= 1) {
        ax += __shfl_xor_sync(0xffffffffu, ax, d);
        ay += __shfl_xor_sync(0xffffffffu, ay, d);
        az += __shfl_xor_sync(0xffffffffu, az, d);
        aw += __shfl_xor_sync(0xffffffffu, aw, d);
    }
    if (sub == 0)
        *reinterpret_cast<float4*>(outx + (size_t)i * 4) =
            make_float4(ax, ay, az, aw);
}

// thread per output PAIR; coalesced W0 reads; writes fp16
__global__ void gemm0f_kernel(const float* __restrict__ xa,
                              const float* __restrict__ W0,
                              const float* __restrict__ b0,
                              __half* __restrict__ out) {
    int idx = blockIdx.x * blockDim.x + threadIdx.x;
    if (idx >= N_NODES * (EMB / 2)) return;
    int i = idx / (EMB / 2), p = idx - i * (EMB / 2);
    int f0 = 2 * p;
    const float* xr = xa + (size_t)i * 4;
    float x0 = xr[0], x1 = xr[1], x2 = xr[2], x3 = xr[3];
    float s0 = x0 * __ldg(&W0[f0])
             + x1 * __ldg(&W0[EMB + f0])
             + x2 * __ldg(&W0[2 * EMB + f0])
             + x3 * __ldg(&W0[3 * EMB + f0])
             + __ldg(&b0[f0]);
    float s1 = x0 * __ldg(&W0[f0 + 1])
             + x1 * __ldg(&W0[EMB + f0 + 1])
             + x2 * __ldg(&W0[2 * EMB + f0 + 1])
             + x3 * __ldg(&W0[3 * EMB + f0 + 1])
             + __ldg(&b0[f0 + 1]);
    s0 = s0 > 0.f ? s0 : 0.01f * s0;
    s1 = s1 > 0.f ? s1 : 0.01f * s1;
    __half2 o = __floats2half2_rn(s0, s1);
    *reinterpret_cast<__half2*>(&out[(size_t)i * EMB + f0]) = o;
}

// ---------------- layers 1-3: fp16 GEMM via mma.sync.m16n8k16 --------------
// A exact fp16; W plain fp16 (weight-rounding err ~1.4e-4/layer, budget 1e-3).
// 1 MMA per (t,f) tile -> half the MMA stream of the hi/lo variant.
#define GBM   64
#define ASTR  12
#define BSTR  216

#define MMA_F16(d, a0, a1, a2, a3, b0, b1)                                    \
    asm volatile("mma.sync.aligned.m16n8k16.row.col.f32.f16.f16.f32 "        \
                 "{%0,%1,%2,%3}, {%4,%5,%6,%7}, {%8,%9}, {%0,%1,%2,%3};"     \
                 : "+f"((d)[0]), "+f"((d)[1]), "+f"((d)[2]), "+f"((d)[3])    \
                 : "r"(a0), "r"(a1), "r"(a2), "r"(a3), "r"(b0), "r"(b1))

__global__ __launch_bounds__(128) void gemm_f16_kernel(
    const __half* __restrict__ h,
    const uint32_t* __restrict__ whi,
    __half* __restrict__ out) {
    __shared__ uint32_t sA [2][GBM * ASTR];
    __shared__ uint32_t sBh[2][8 * BSTR];

    int tid  = threadIdx.x;
    int lane = tid & 31, warp = tid >> 5;
    int wm = warp >> 1;
    int wn = warp & 1;
    int row0 = blockIdx.x * GBM;
    int gid = lane >> 2;
    int tig = lane & 3;

    float acc[13][2][4];
#pragma unroll
    for (int t = 0; t < 13; t++)
#pragma unroll
        for (int f = 0; f < 2; f++) {
            acc[t][f][0] = 0.f; acc[t][f][1] = 0.f;
            acc[t][f][2] = 0.f; acc[t][f][3] = 0.f;
        }

    uint32_t ra[4];
    uint32_t rbh[13];

    auto FETCH = [&](int chunk) {
        int k0 = chunk * 16;
#pragma unroll
        for (int i = 0; i < 4; i++) {
            int idx = tid + i * 128;
            int r = idx >> 3, kp = idx & 7;
            int gr = row0 + r;
            int ka = k0 + 2 * kp;
            ra[i] = (gr < N_NODES && ka < EMB)
                  ? __ldg(reinterpret_cast<const uint32_t*>(h + (size_t)gr * EMB + ka))
                  : 0u;
        }
        int base = chunk * 8 * NPAD;
#pragma unroll
        for (int i = 0; i < 13; i++) {
            int idx = tid + i * 128;
            int r = idx / NPAD, c = idx - r * NPAD;
            rbh[i] = __ldg(&whi[base + r * NPAD + c]);
        }
    };
    auto STORE = [&](int buf) {
#pragma unroll
        for (int i = 0; i < 4; i++) {
            int idx = tid + i * 128;
            int r = idx >> 3, kp = idx & 7;
            sA[buf][r * ASTR + kp] = ra[i];
        }
#pragma unroll
        for (int i = 0; i < 13; i++) {
            int idx = tid + i * 128;
            int r = idx / NPAD, c = idx - r * NPAD;
            sBh[buf][r * BSTR + c] = rbh[i];
        }
    };

    FETCH(0);
    STORE(0);
    __syncthreads();

    int ar = wm * 32 + gid;
#pragma unroll 1
    for (int ks = 0; ks < 13; ks++) {
        int cur = ks & 1;
        if (ks < 12) FETCH(ks + 1);

        uint32_t a[8];
#pragma unroll
        for (int f = 0; f < 2; f++) {
            int r = ar + f * 16;
            a[f * 4 + 0] = sA[cur][r * ASTR + tig];
            a[f * 4 + 1] = sA[cur][(r + 8) * ASTR + tig];
            a[f * 4 + 2] = sA[cur][r * ASTR + tig + 4];
            a[f * 4 + 3] = sA[cur][(r + 8) * ASTR + tig + 4];
        }

#pragma unroll
        for (int t = 0; t < 13; t++) {
            int n = wn * 104 + t * 8 + gid;
            uint32_t bh0 = sBh[cur][tig * BSTR + n];
            uint32_t bh1 = sBh[cur][(tig + 4) * BSTR + n];
            MMA_F16(acc[t][0], a[0], a[1], a[2], a[3], bh0, bh1);
            MMA_F16(acc[t][1], a[4], a[5], a[6], a[7], bh0, bh1);
        }

        if (ks < 12) STORE(cur ^ 1);
        __syncthreads();
    }

#pragma unroll
    for (int t = 0; t < 13; t++) {
        int n = wn * 104 + t * 8 + 2 * tig;
        if (n >= EMB) continue;
#pragma unroll
        for (int f = 0; f < 2; f++) {
            int r = row0 + wm * 32 + f * 16 + gid;
            if (r < N_NODES) {
                __half2 v = __floats2half2_rn(acc[t][f][0], acc[t][f][1]);
                *reinterpret_cast<__half2*>(&out[(size_t)r * EMB + n]) = v;
            }
            if (r + 8 < N_NODES) {
                __half2 v = __floats2half2_rn(acc[t][f][2], acc[t][f][3]);
                *reinterpret_cast<__half2*>(&out[(size_t)(r + 8) * EMB + n]) = v;
            }
        }
    }
}

// ---------------- edge aggregation (fp16 gather, warp per dst node) --------
__device__ __forceinline__ void unpack8(uint4 v, float* f) {
    float2 t;
    t = __half22float2(*reinterpret_cast<__half2*>(&v.x)); f[0] = t.x; f[1] = t.y;
    t = __half22float2(*reinterpret_cast<__half2*>(&v.y)); f[2] = t.x; f[3] = t.y;
    t = __half22float2(*reinterpret_cast<__half2*>(&v.z)); f[4] = t.x; f[5] = t.y;
    t = __half22float2(*reinterpret_cast<__half2*>(&v.w)); f[6] = t.x; f[7] = t.y;
}

__global__ __launch_bounds__(256) void aggregate_h_kernel(
    const __half* __restrict__ hw, const float* __restrict__ b,
    __half* __restrict__ out) {
    int warp = (blockIdx.x * blockDim.x + threadIdx.x) >> 5;
    int lane = threadIdx.x & 31;
    if (warp >= N_NODES || lane >= 25) return;
    int i = warp;

    float dv = g_dinv[i];
    float selfc = dv * dv;

    const uint4* h4 = reinterpret_cast<const uint4*>(hw);
    float acc[8], f[8];
    {
        uint4 v = __ldg(&h4[(size_t)i * 25 + lane]);
        unpack8(v, f);
#pragma unroll
        for (int j = 0; j < 8; j++) acc[j] = selfc * f[j];
    }

    int e0 = g_off[i], e1 = g_off[i + 1];
    for (int e = e0; e < e1; e++) {
        int2 sc = __ldg(&g_csr[e]);
        int   s = sc.x;
        float c = __int_as_float(sc.y);
        uint4 v = __ldg(&h4[(size_t)s * 25 + lane]);
        unpack8(v, f);
#pragma unroll
        for (int j = 0; j < 8; j++) acc[j] += c * f[j];
    }

    int f0 = lane * 8;
    float4 b0 = *reinterpret_cast<const float4*>(b + f0);
    float4 b1 = *reinterpret_cast<const float4*>(b + f0 + 4);
    acc[0] += b0.x; acc[1] += b0.y; acc[2] += b0.z; acc[3] += b0.w;
    acc[4] += b1.x; acc[5] += b1.y; acc[6] += b1.z; acc[7] += b1.w;
#pragma unroll
    for (int j = 0; j < 8; j++) acc[j] = acc[j] > 0.f ? acc[j] : 0.01f * acc[j];

    uint4 pv;
    __half2 p;
    p = __floats2half2_rn(acc[0], acc[1]); pv.x = *reinterpret_cast<uint32_t*>(&p);
    p = __floats2half2_rn(acc[2], acc[3]); pv.y = *reinterpret_cast<uint32_t*>(&p);
    p = __floats2half2_rn(acc[4], acc[5]); pv.z = *reinterpret_cast<uint32_t*>(&p);
    p = __floats2half2_rn(acc[6], acc[7]); pv.w = *reinterpret_cast<uint32_t*>(&p);
    reinterpret_cast<uint4*>(out)[(size_t)i * 25 + lane] = pv;
}

// ---------------- pooling + MLP head (fused, block per graph) --------------
__global__ __launch_bounds__(256) void poolmlp_kernel(
    const __half* __restrict__ h, const float* __restrict__ xs,
    const float* __restrict__ Wl1, const float* __restrict__ bl1,
    const float* __restrict__ Wl2, const float* __restrict__ bl2,
    float* __restrict__ out) {
    int g = blockIdx.x;
    int t = threadIdx.x;
    __shared__ float gv[EMB + N_FEAT];
    __shared__ float red[HID];

    int r0 = g_goff[g];
    int n  = g_goff[g + 1] - r0;
    if (t < EMB) {
        float s = 0.f;
        for (int j = 0; j < n; j++) s += __half2float(h[(size_t)(r0 + j) * EMB + t]);
        gv[t] = s / fmaxf((float)n, 1.0f);
    } else if (t < EMB + N_FEAT) {
        gv[t] = xs[g * N_FEAT + (t - EMB)];
    }
    __syncthreads();

    if (t < HID) {
        float acc = bl1[t];
        for (int k = 0; k < EMB + N_FEAT; k++) acc += gv[k] * Wl1[k * HID + t];
        acc = acc > 0.f ? acc : 0.01f * acc;
        red[t] = acc * Wl2[t];
    }
    __syncthreads();
    for (int s = HID / 2; s > 0; s >>= 1) {
        if (t < s) red[t] += red[t + s];
        __syncthreads();
    }
    if (t == 0) out[g] = red[0] + bl2[0];
}

// ---------------- launcher --------------------------------------------------
extern "C" void kernel_launch(void* const* d_in, const int* in_sizes, int n_in,
                              void* d_out, int out_size) {
    const float* x        = (const float*)d_in[0];
    const void*  ei       = d_in[1];
    const float* x_scalar = (const float*)d_in[2];
    const void*  bi       = d_in[3];
    const float* W0  = (const float*)d_in[4];
    const float* b0  = (const float*)d_in[5];
    const float* W1  = (const float*)d_in[6];
    const float* b1  = (const float*)d_in[7];
    const float* W2  = (const float*)d_in[8];
    const float* b2  = (const float*)d_in[9];
    const float* W3  = (const float*)d_in[10];
    const float* b3  = (const float*)d_in[11];
    const float* Wl1 = (const float*)d_in[12];
    const float* bl1 = (const float*)d_in[13];
    const float* Wl2 = (const float*)d_in[14];
    const float* bl2 = (const float*)d_in[15];
    float* out = (float*)d_out;

    __half *bufA, *bufB, *hw;
    float* aggx;
    uint32_t* whi;
    cudaGetSymbolAddress((void**)&bufA, g_bufA);
    cudaGetSymbolAddress((void**)&bufB, g_bufB);
    cudaGetSymbolAddress((void**)&hw,   g_hw);
    cudaGetSymbolAddress((void**)&aggx, g_aggx);
    cudaGetSymbolAddress((void**)&whi,  g_Whi);

    const int TB = 256;
    int gridN  = (N_NODES + TB - 1) / TB;
    int gridC  = (N_EDGES / 4 + TB - 1) / TB;          // 391 (also covers nodes)
    int gridS  = (N_EDGES / 2 + TB - 1) / TB;          // 782
    int gridA4 = (N_NODES * 4 + TB - 1) / TB;          // 782 (4 thr/node)
    int gridG0 = (N_NODES * (EMB / 2) + TB - 1) / TB;
    int gridAg = (N_NODES * 32 + TB - 1) / TB;
    int gridGm = (N_NODES + GBM - 1) / GBM;            // 782
    int gridW  = (3 * NKP * NPAD + TB - 1) / TB;

    // preprocessing (7 launches)
    init_kernel<<<gridN, TB>>>(ei, bi);
    split_w_kernel<<<gridW, TB>>>(W1, W2, W3);
    count_kernel<<<gridC, TB>>>(ei, bi);
    scan_part_kernel<<<SCAN_NB, SCAN_B>>>();
    scan_top_kernel<<<1, 64>>>();
    scan_final_kernel<<<SCAN_NB, SCAN_B>>>();
    scatter_kernel<<<gridS, TB>>>(ei);

    const int WTOT = NKP * NPAD;

    // layer 0 (aggregate-first by linearity; bias+leaky fused into gemm0f)
    aggregate4_kernel<<<gridA4, TB>>>(x, aggx);
    gemm0f_kernel<<<gridG0, TB>>>(aggx, W0, b0, bufA);

    // layer 1
    gemm_f16_kernel<<<gridGm, 128>>>(bufA, whi, hw);
    aggregate_h_kernel<<<gridAg, TB>>>(hw, b1, bufB);
    // layer 2
    gemm_f16_kernel<<<gridGm, 128>>>(bufB, whi + WTOT, hw);
    aggregate_h_kernel<<<gridAg, TB>>>(hw, b2, bufA);
    // layer 3
    gemm_f16_kernel<<<gridGm, 128>>>(bufA, whi + 2 * WTOT, hw);
    aggregate_h_kernel<<<gridAg, TB>>>(hw, b3, bufB);

    // pool + MLP head (fused)
    poolmlp_kernel<<<N_GRAPHS, TB>>>(bufB, x_scalar, Wl1, bl1, Wl2, bl2, out);
}